// round 14
// baseline (speedup 1.0000x reference)
// rE — LDetection_12103217840297: spatially-indexed exact ATSS, FLOAT32 output
// R13 insight: __output__ dtype is f32, not f64 — all 13 prior rounds wrote
// doubles, which the comparator read as float pairs (0.0f, highword) giving the
// constant rel_err 1.001095. The compute was right; the encoding was wrong.
#include <cuda_runtime.h>
#include <cstdint>
#include <math.h>

#define RE_MAXN 131072
#define RE_MAXM 1024
#define RE_K    9
#define RE_G    64                  // grid is RE_G x RE_G cells
#define RE_NBIN (RE_G * RE_G)
#define RE_CELL 16.0f               // 1024 / 64

// ---------------------------------------------------------------------------
// Scratch (__device__ globals only; no allocations anywhere)
// ---------------------------------------------------------------------------
__device__ float2 rE_ctr[RE_MAXN];      // anchor centers (by anchor idx)
__device__ int    rE_cnt[RE_NBIN];      // per-cell anchor counts
__device__ int    rE_off[RE_NBIN + 1];  // CSR offsets
__device__ int    rE_cur[RE_NBIN];      // scatter cursors
__device__ float2 rE_bc[RE_MAXN];       // binned centers
__device__ int    rE_bi[RE_MAXN];       // binned anchor indices
__device__ float  rE_thr[RE_MAXM];      // per-gt IoU threshold
__device__ int    rE_best[RE_MAXN];     // per-anchor matched gt (atomicMax), -1 = none
__device__ int    rE_nmatch;            // matched count (diagnostic canary)

__device__ __forceinline__ int rE_cellidx(float v) {
    int c = (int)floorf(__fmul_rn(v, 1.0f / RE_CELL));
    return min(RE_G - 1, max(0, c));
}

// ---------------------------------------------------------------------------
// K1: reset counters / per-anchor state (runs every graph replay)
// ---------------------------------------------------------------------------
__global__ void rE_reset(int N) {
    int i = blockIdx.x * blockDim.x + threadIdx.x;
    if (i == 0) rE_nmatch = 0;
    if (i < RE_NBIN) rE_cnt[i] = 0;
    if (i < N) rE_best[i] = -1;
}

// ---------------------------------------------------------------------------
// K2: centers ((x0+x1)*0.5 == /2 in IEEE) + per-cell counts
// ---------------------------------------------------------------------------
__global__ void rE_count(const float4* __restrict__ anchors, int N) {
    int i = blockIdx.x * blockDim.x + threadIdx.x;
    if (i >= N) return;
    float4 a = anchors[i];
    float cx = __fmul_rn(__fadd_rn(a.x, a.z), 0.5f);
    float cy = __fmul_rn(__fadd_rn(a.y, a.w), 0.5f);
    rE_ctr[i] = make_float2(cx, cy);
    atomicAdd(&rE_cnt[rE_cellidx(cy) * RE_G + rE_cellidx(cx)], 1);
}

// ---------------------------------------------------------------------------
// K3: single-block exclusive scan of 4096 counts (256 threads x 16 bins each)
// ---------------------------------------------------------------------------
__global__ __launch_bounds__(256) void rE_scan() {
    __shared__ int s_tot[256];
    const int t = threadIdx.x;
    int loc[16];
    int tot = 0;
#pragma unroll
    for (int j = 0; j < 16; j++) {
        int c = rE_cnt[t * 16 + j];
        loc[j] = tot;
        tot += c;
    }
    s_tot[t] = tot;
    __syncthreads();
    for (int off = 1; off < 256; off <<= 1) {
        int v = (t >= off) ? s_tot[t - off] : 0;
        __syncthreads();
        s_tot[t] += v;
        __syncthreads();
    }
    int base = (t > 0) ? s_tot[t - 1] : 0;
#pragma unroll
    for (int j = 0; j < 16; j++) {
        int o = base + loc[j];
        rE_off[t * 16 + j] = o;
        rE_cur[t * 16 + j] = o;
    }
    if (t == 255) rE_off[RE_NBIN] = s_tot[255];
}

// ---------------------------------------------------------------------------
// K4: scatter into CSR. Slot order non-deterministic; all consumers are
// order-independent (total-order top-k, atomicMax) => outputs deterministic.
// ---------------------------------------------------------------------------
__global__ void rE_scatter(int N) {
    int i = blockIdx.x * blockDim.x + threadIdx.x;
    if (i >= N) return;
    float2 c = rE_ctr[i];
    int cell = rE_cellidx(c.y) * RE_G + rE_cellidx(c.x);
    int slot = atomicAdd(&rE_cur[cell], 1);
    rE_bc[slot] = c;
    rE_bi[slot] = i;
}

// ---------------------------------------------------------------------------
// K5: per-gt exact top-9 by (f32 sqrt-domain distance, low idx) == lax.top_k
// with stable ties. Expanding Chebyshev rings; ring-r cells are >=(r-1)*CELL
// away, stop when 9 held and (r-1)*CELL > d9 (strict). Then
// thr = mean + std(ddof=1) of the 9 IoUs, sequential f32, no fma.
// ---------------------------------------------------------------------------
__global__ __launch_bounds__(128) void rE_thresh(
    const float4* __restrict__ anchors,
    const float4* __restrict__ gts,
    int N, int M)
{
    int g = blockIdx.x * blockDim.x + threadIdx.x;
    if (g >= M) return;

    const float4 gb = gts[g];
    const float gcx = __fmul_rn(__fadd_rn(gb.x, gb.z), 0.5f);
    const float gcy = __fmul_rn(__fadd_rn(gb.y, gb.w), 0.5f);
    const int ccx = rE_cellidx(gcx);
    const int ccy = rE_cellidx(gcy);

    const float INF = __int_as_float(0x7F800000);
    float kd[RE_K]; int kid[RE_K];
#pragma unroll
    for (int j = 0; j < RE_K; j++) { kd[j] = INF; kid[j] = 0x7FFFFFFF; }
    int nheld = 0;

    auto scan_cell = [&](int cx, int cy) {
        int cell = cy * RE_G + cx;
        int s = rE_off[cell], e = rE_off[cell + 1];
        for (int slot = s; slot < e; slot++) {
            float2 c = rE_bc[slot];
            int idx = rE_bi[slot];
            float dx = __fadd_rn(c.x, -gcx);
            float dy = __fadd_rn(c.y, -gcy);
            float d2 = __fadd_rn(__fmul_rn(dx, dx), __fmul_rn(dy, dy));
            float d = __fsqrt_rn(d2);            // reference ranks in sqrt domain
            if (d < kd[RE_K-1] || (d == kd[RE_K-1] && idx < kid[RE_K-1])) {
                int j = RE_K - 1;
                while (j > 0 && (d < kd[j-1] || (d == kd[j-1] && idx < kid[j-1]))) {
                    kd[j] = kd[j-1]; kid[j] = kid[j-1]; --j;
                }
                kd[j] = d; kid[j] = idx;
                if (nheld < RE_K) nheld++;
            }
        }
    };

    for (int r = 0; r <= RE_G; r++) {
        if (r >= 1 && nheld == RE_K && kd[RE_K-1] < INF &&
            __fmul_rn((float)(r - 1), RE_CELL) > kd[RE_K-1]) break;
        if (r == 0) { scan_cell(ccx, ccy); continue; }
        int x0 = ccx - r, x1 = ccx + r, y0 = ccy - r, y1 = ccy + r;
        int xa = max(x0, 0), xb = min(x1, RE_G - 1);
        if (y0 >= 0)        for (int x = xa; x <= xb; x++) scan_cell(x, y0);
        if (y1 <= RE_G - 1) for (int x = xa; x <= xb; x++) scan_cell(x, y1);
        int ya = max(y0 + 1, 0), yb = min(y1 - 1, RE_G - 1);
        if (x0 >= 0)        for (int y = ya; y <= yb; y++) scan_cell(x0, y);
        if (x1 <= RE_G - 1) for (int y = ya; y <= yb; y++) scan_cell(x1, y);
    }

    const float area_g = __fmul_rn(__fadd_rn(gb.z, -gb.x), __fadd_rn(gb.w, -gb.y));
    float iou[RE_K];
#pragma unroll
    for (int j = 0; j < RE_K; j++) {
        int idx = kid[j];
        if (idx < 0 || idx >= N) idx = 0;        // unreachable guard
        float4 a = anchors[idx];
        float lx = fmaxf(a.x, gb.x), ly = fmaxf(a.y, gb.y);
        float rx = fminf(a.z, gb.z), ry = fminf(a.w, gb.w);
        float w = fmaxf(__fadd_rn(rx, -lx), 0.0f);
        float h = fmaxf(__fadd_rn(ry, -ly), 0.0f);
        float inter = __fmul_rn(w, h);
        float area_a = __fmul_rn(__fadd_rn(a.z, -a.x), __fadd_rn(a.w, -a.y));
        float uni = __fadd_rn(__fadd_rn(area_a, area_g), -inter);
        iou[j] = __fdiv_rn(inter, fmaxf(uni, 1e-12f));
    }
    float sum = 0.0f;
#pragma unroll
    for (int j = 0; j < RE_K; j++) sum = __fadd_rn(sum, iou[j]);
    float mean = __fdiv_rn(sum, (float)RE_K);
    float ss = 0.0f;
#pragma unroll
    for (int j = 0; j < RE_K; j++) {
        float d = __fadd_rn(iou[j], -mean);
        ss = __fadd_rn(ss, __fmul_rn(d, d));
    }
    float var = __fdiv_rn(ss, (float)(RE_K - 1));
    rE_thr[g] = __fadd_rn(mean, __fsqrt_rn(var));
}

// ---------------------------------------------------------------------------
// K6: inverted assignment — one warp per gt over cells overlapping the gt box;
// center-inside && iou >= thr  =>  atomicMax(best[anchor], g)  (== max-g-over-pos)
// ---------------------------------------------------------------------------
__global__ __launch_bounds__(256) void rE_assign(
    const float4* __restrict__ anchors,
    const float4* __restrict__ gts,
    int N, int M)
{
    const int wid = blockIdx.x * (blockDim.x / 32) + (threadIdx.x / 32);
    const int lane = threadIdx.x & 31;
    if (wid >= M) return;
    const int g = wid;

    const float4 gb = gts[g];
    const float thr = rE_thr[g];
    const float area_g = __fmul_rn(__fadd_rn(gb.z, -gb.x), __fadd_rn(gb.w, -gb.y));

    const int cx0 = rE_cellidx(gb.x), cx1 = rE_cellidx(gb.z);
    const int cy0 = rE_cellidx(gb.y), cy1 = rE_cellidx(gb.w);

    for (int cy = cy0; cy <= cy1; cy++) {
        for (int cx = cx0; cx <= cx1; cx++) {
            int cell = cy * RE_G + cx;
            int s = rE_off[cell], e = rE_off[cell + 1];
            for (int slot = s + lane; slot < e; slot += 32) {
                float2 c = rE_bc[slot];
                bool inside = (c.x >= gb.x) && (c.x <= gb.z) &&
                              (c.y >= gb.y) && (c.y <= gb.w);
                if (!inside) continue;
                int idx = rE_bi[slot];
                float4 a = anchors[idx];
                float lx = fmaxf(a.x, gb.x), ly = fmaxf(a.y, gb.y);
                float rx = fminf(a.z, gb.z), ry = fminf(a.w, gb.w);
                float w = fmaxf(__fadd_rn(rx, -lx), 0.0f);
                float h = fmaxf(__fadd_rn(ry, -ly), 0.0f);
                float inter = __fmul_rn(w, h);
                float area_a = __fmul_rn(__fadd_rn(a.z, -a.x), __fadd_rn(a.w, -a.y));
                float uni = __fadd_rn(__fadd_rn(area_a, area_g), -inter);
                float iou = __fdiv_rn(inter, fmaxf(uni, 1e-12f));
                if (iou >= thr) atomicMax(&rE_best[idx], g);
            }
        }
    }
}

// ---------------------------------------------------------------------------
// K7: finalize — recompute the matched IoU exactly and write
// [matched | max_ious] as FLOAT32 (the actual __output__ dtype).
// ---------------------------------------------------------------------------
__global__ __launch_bounds__(256) void rE_final(
    const float4* __restrict__ anchors,
    const float4* __restrict__ gts,
    int N, int out_elems,
    float* __restrict__ out)
{
    int i = blockIdx.x * blockDim.x + threadIdx.x;
    if (i >= N) return;
    int g = rE_best[i];
    float iou_out = 0.0f;
    if (g >= 0) {
        float4 a = anchors[i];
        float4 gb = gts[g];
        float lx = fmaxf(a.x, gb.x), ly = fmaxf(a.y, gb.y);
        float rx = fminf(a.z, gb.z), ry = fminf(a.w, gb.w);
        float w = fmaxf(__fadd_rn(rx, -lx), 0.0f);
        float h = fmaxf(__fadd_rn(ry, -ly), 0.0f);
        float inter = __fmul_rn(w, h);
        float area_a = __fmul_rn(__fadd_rn(a.z, -a.x), __fadd_rn(a.w, -a.y));
        float area_g = __fmul_rn(__fadd_rn(gb.z, -gb.x), __fadd_rn(gb.w, -gb.y));
        float uni = __fadd_rn(__fadd_rn(area_a, area_g), -inter);
        iou_out = __fdiv_rn(inter, fmaxf(uni, 1e-12f));
        atomicAdd(&rE_nmatch, 1);
    }
    if (i < out_elems)     out[i]     = (float)g;
    if (N + i < out_elems) out[N + i] = iou_out;
}

// Diagnostic: zero matches would force a visible ~1e8 sentinel (now a real f32).
__global__ void rE_canary(float* __restrict__ out, int out_elems) {
    if (threadIdx.x == 0 && blockIdx.x == 0 && rE_nmatch == 0 && out_elems > 0)
        out[0] = 1.0e8f;
}

// ---------------------------------------------------------------------------
extern "C" void kernel_launch(void* const* d_in, const int* in_sizes, int n_in,
                              void* d_out, int out_size) {
    int ia = 0, ig = 1;
    if (n_in >= 2 && in_sizes[1] > in_sizes[0]) { ia = 1; ig = 0; }
    const float4* anchors = (const float4*)d_in[ia];
    const float4* gts     = (const float4*)d_in[ig];
    int N = in_sizes[ia] / 4; if (N > RE_MAXN) N = RE_MAXN;
    int M = in_sizes[ig] / 4; if (M > RE_MAXM) M = RE_MAXM;
    float* out = (float*)d_out;

    const int NB = (N + 255) / 256;
    const int PB = ((N > RE_NBIN ? N : RE_NBIN) + 255) / 256;
    rE_reset<<<PB, 256>>>(N);
    rE_count<<<NB, 256>>>(anchors, N);
    rE_scan<<<1, 256>>>();
    rE_scatter<<<NB, 256>>>(N);
    rE_thresh<<<(M + 127) / 128, 128>>>(anchors, gts, N, M);
    rE_assign<<<(M + 7) / 8, 256>>>(anchors, gts, N, M);
    rE_final<<<NB, 256>>>(anchors, gts, N, out_size, out);
    rE_canary<<<1, 32>>>(out, out_size);
}

// round 15
// speedup vs baseline: 3.0648x; 3.0648x over previous
// rF — LDetection_12103217840297: fused warp-per-gt ATSS (f32 output, exact)
#include <cuda_runtime.h>
#include <cstdint>
#include <math.h>

#define RF_MAXN 131072
#define RF_MAXM 1024
#define RF_K    9
#define RF_G    64
#define RF_NBIN (RF_G * RF_G)
#define RF_CELL 16.0f

// ---------------------------------------------------------------------------
// Scratch (__device__ globals only)
// ---------------------------------------------------------------------------
__device__ int    rF_cnt[RF_NBIN];
__device__ int    rF_off[RF_NBIN + 1];
__device__ int    rF_cur[RF_NBIN];
__device__ float2 rF_bc[RF_MAXN];       // binned centers
__device__ int    rF_bi[RF_MAXN];       // binned anchor indices
__device__ float4 rF_ba[RF_MAXN];       // binned anchor boxes
__device__ int    rF_best[RF_MAXN];     // matched gt per anchor (atomicMax)

__device__ __forceinline__ int rF_cellidx(float v) {
    int c = (int)floorf(__fmul_rn(v, 1.0f / RF_CELL));
    return min(RF_G - 1, max(0, c));
}

// K1: zero per-cell counts
__global__ void rF_reset() {
    int i = blockIdx.x * blockDim.x + threadIdx.x;
    if (i < RF_NBIN) rF_cnt[i] = 0;
}

// K2: centers -> counts; fold best=-1 init
__global__ void rF_count(const float4* __restrict__ anchors, int N) {
    int i = blockIdx.x * blockDim.x + threadIdx.x;
    if (i >= N) return;
    rF_best[i] = -1;
    float4 a = anchors[i];
    float cx = __fmul_rn(__fadd_rn(a.x, a.z), 0.5f);
    float cy = __fmul_rn(__fadd_rn(a.y, a.w), 0.5f);
    atomicAdd(&rF_cnt[rF_cellidx(cy) * RF_G + rF_cellidx(cx)], 1);
}

// K3: single-block exclusive scan (256 threads x 16 bins)
__global__ __launch_bounds__(256) void rF_scan() {
    __shared__ int s_tot[256];
    const int t = threadIdx.x;
    int loc[16];
    int tot = 0;
#pragma unroll
    for (int j = 0; j < 16; j++) { int c = rF_cnt[t * 16 + j]; loc[j] = tot; tot += c; }
    s_tot[t] = tot;
    __syncthreads();
    for (int off = 1; off < 256; off <<= 1) {
        int v = (t >= off) ? s_tot[t - off] : 0;
        __syncthreads();
        s_tot[t] += v;
        __syncthreads();
    }
    int base = (t > 0) ? s_tot[t - 1] : 0;
#pragma unroll
    for (int j = 0; j < 16; j++) {
        int o = base + loc[j];
        rF_off[t * 16 + j] = o;
        rF_cur[t * 16 + j] = o;
    }
    if (t == 255) rF_off[RF_NBIN] = s_tot[255];
}

// K4: scatter (centers recomputed; store center + idx + box). Slot order is
// non-deterministic; all consumers are order-independent => deterministic output.
__global__ void rF_scatter(const float4* __restrict__ anchors, int N) {
    int i = blockIdx.x * blockDim.x + threadIdx.x;
    if (i >= N) return;
    float4 a = anchors[i];
    float cx = __fmul_rn(__fadd_rn(a.x, a.z), 0.5f);
    float cy = __fmul_rn(__fadd_rn(a.y, a.w), 0.5f);
    int cell = rF_cellidx(cy) * RF_G + rF_cellidx(cx);
    int slot = atomicAdd(&rF_cur[cell], 1);
    rF_bc[slot] = make_float2(cx, cy);
    rF_bi[slot] = i;
    rF_ba[slot] = a;
}

// ---------------------------------------------------------------------------
// K5: fused per-gt kernel, ONE WARP PER GT.
//  Phase A: expanding-ring exact top-9 by (f32 sqrt-domain distance, low idx)
//           == lax.top_k(-d) with stable ties. Lanes stride slots (coalesced);
//           each lane keeps a register-resident sorted list of packed u64 keys
//           (static-index compare-exchange only). Ring-end merge = 9 rounds of
//           warp-min head-consume on a COPY (lists preserved for slow path).
//           Stop when 9 held and r*CELL > d9 (strict).
//  Phase B: lane 0 computes thr = mean + std(ddof=1) sequentially in f32.
//  Phase C: assignment — warp walks cells overlapping the gt box;
//           center-inside && iou >= thr => atomicMax(best[anchor], g).
// ---------------------------------------------------------------------------
__global__ __launch_bounds__(256) void rF_gt(
    const float4* __restrict__ gts, int N, int M)
{
    const int warp = blockIdx.x * (blockDim.x >> 5) + (threadIdx.x >> 5);
    const int lane = threadIdx.x & 31;
    if (warp >= M) return;
    const int g = warp;

    const float4 gb = gts[g];
    const float gcx = __fmul_rn(__fadd_rn(gb.x, gb.z), 0.5f);
    const float gcy = __fmul_rn(__fadd_rn(gb.y, gb.w), 0.5f);
    const int ccx = rF_cellidx(gcx);
    const int ccy = rF_cellidx(gcy);

    const unsigned long long SENT = 0xFFFFFFFFFFFFFFFFull;
    unsigned long long K[RF_K];
#pragma unroll
    for (int j = 0; j < RF_K; j++) K[j] = SENT;

    auto scan_cell = [&](int cx, int cy) {
        int cell = cy * RF_G + cx;
        int s = rF_off[cell], e = rF_off[cell + 1];
        for (int slot = s + lane; slot < e; slot += 32) {
            float2 c = rF_bc[slot];
            int idx = rF_bi[slot];
            float dx = __fadd_rn(c.x, -gcx);
            float dy = __fadd_rn(c.y, -gcy);
            float d2 = __fadd_rn(__fmul_rn(dx, dx), __fmul_rn(dy, dy));
            float d = __fsqrt_rn(d2);
            unsigned long long key =
                ((unsigned long long)__float_as_uint(d) << 32) | (unsigned)idx;
            if (key < K[RF_K - 1]) {
                K[RF_K - 1] = key;
#pragma unroll
                for (int j = RF_K - 1; j > 0; j--) {
                    unsigned long long lo = K[j - 1], hi = K[j];
                    if (hi < lo) { K[j - 1] = hi; K[j] = lo; }
                }
            }
        }
    };

    unsigned long long sel[RF_K];
    auto merge = [&]() {
        unsigned long long T[RF_K];
#pragma unroll
        for (int j = 0; j < RF_K; j++) T[j] = K[j];
#pragma unroll
        for (int t = 0; t < RF_K; t++) {
            unsigned long long m = T[0];
#pragma unroll
            for (int o = 16; o > 0; o >>= 1) {
                unsigned long long v = __shfl_xor_sync(0xFFFFFFFFu, m, o);
                if (v < m) m = v;
            }
            if (T[0] == m) {          // unique key -> exactly one consumer
#pragma unroll
                for (int j = 0; j < RF_K - 1; j++) T[j] = T[j + 1];
                T[RF_K - 1] = SENT;
            }
            sel[t] = m;               // broadcast to all lanes by the butterfly
        }
    };

    for (int r = 0; r <= 2 * RF_G; r++) {
        if (r == 0) {
            scan_cell(ccx, ccy);
        } else {
            int x0 = ccx - r, x1 = ccx + r, y0 = ccy - r, y1 = ccy + r;
            int xa = max(x0, 0), xb = min(x1, RF_G - 1);
            if (y0 >= 0)        for (int x = xa; x <= xb; x++) scan_cell(x, y0);
            if (y1 <= RF_G - 1) for (int x = xa; x <= xb; x++) scan_cell(x, y1);
            int ya = max(y0 + 1, 0), yb = min(y1 - 1, RF_G - 1);
            if (x0 >= 0)        for (int y = ya; y <= yb; y++) scan_cell(x0, y);
            if (x1 <= RF_G - 1) for (int y = ya; y <= yb; y++) scan_cell(x1, y);
        }
        if (r >= 2) {                 // common path: one merge at r==2, break
            merge();
            if (sel[RF_K - 1] != SENT) {
                float d9 = __uint_as_float((unsigned)(sel[RF_K - 1] >> 32));
                if (__fmul_rn((float)r, RF_CELL) > d9) break;
            }
        }
    }

    // Phase B: IoUs of the 9 selected anchors (lanes 0..8), thr in lane 0
    const float area_g = __fmul_rn(__fadd_rn(gb.z, -gb.x), __fadd_rn(gb.w, -gb.y));
    float my_iou = 0.0f;
    if (lane < RF_K) {
        int idx = (int)(unsigned)(sel[lane] & 0xFFFFFFFFull);
        if (idx < 0 || idx >= N) idx = 0;       // unreachable guard
        // anchors by original index: gather via binned copy is unavailable here,
        // but 9 gathers/gt are negligible — use gts-style direct load through bi.
        // We stored boxes binned; find via slot is gone, so reload from rF_ba is
        // not indexed by anchor id. Keep a direct gather from the input instead:
        // (passed via rF_ba? no) -> use global anchors pointer: provided below.
        my_iou = idx >= 0 ? 0.0f : 0.0f;        // placeholder, overwritten next
    }
    // NOTE: anchor boxes by ORIGINAL id needed only here (9 loads) and in final.
    // We re-derive them from the binned arrays is impossible; instead the kernel
    // receives the raw anchors pointer through a __device__ global set below.
    extern __device__ const float4* rF_anchors_p;
    if (lane < RF_K) {
        int idx = (int)(unsigned)(sel[lane] & 0xFFFFFFFFull);
        if (idx < 0 || idx >= N) idx = 0;
        float4 a = rF_anchors_p[idx];
        float lx = fmaxf(a.x, gb.x), ly = fmaxf(a.y, gb.y);
        float rx = fminf(a.z, gb.z), ry = fminf(a.w, gb.w);
        float w = fmaxf(__fadd_rn(rx, -lx), 0.0f);
        float h = fmaxf(__fadd_rn(ry, -ly), 0.0f);
        float inter = __fmul_rn(w, h);
        float area_a = __fmul_rn(__fadd_rn(a.z, -a.x), __fadd_rn(a.w, -a.y));
        float uni = __fadd_rn(__fadd_rn(area_a, area_g), -inter);
        my_iou = __fdiv_rn(inter, fmaxf(uni, 1e-12f));
    }
    float thr;
    {
        float iou_t[RF_K];
#pragma unroll
        for (int t = 0; t < RF_K; t++)
            iou_t[t] = __shfl_sync(0xFFFFFFFFu, my_iou, t);
        float sum = 0.0f;
#pragma unroll
        for (int t = 0; t < RF_K; t++) sum = __fadd_rn(sum, iou_t[t]);
        float mean = __fdiv_rn(sum, (float)RF_K);
        float ss = 0.0f;
#pragma unroll
        for (int t = 0; t < RF_K; t++) {
            float d = __fadd_rn(iou_t[t], -mean);
            ss = __fadd_rn(ss, __fmul_rn(d, d));
        }
        float var = __fdiv_rn(ss, (float)(RF_K - 1));
        thr = __fadd_rn(mean, __fsqrt_rn(var));
    }

    // Phase C: assignment over cells overlapping the gt box
    const int cx0 = rF_cellidx(gb.x), cx1 = rF_cellidx(gb.z);
    const int cy0 = rF_cellidx(gb.y), cy1 = rF_cellidx(gb.w);
    for (int cy = cy0; cy <= cy1; cy++) {
        for (int cx = cx0; cx <= cx1; cx++) {
            int cell = cy * RF_G + cx;
            int s = rF_off[cell], e = rF_off[cell + 1];
            for (int slot = s + lane; slot < e; slot += 32) {
                float2 c = rF_bc[slot];
                bool inside = (c.x >= gb.x) && (c.x <= gb.z) &&
                              (c.y >= gb.y) && (c.y <= gb.w);
                if (!inside) continue;
                float4 a = rF_ba[slot];
                float lx = fmaxf(a.x, gb.x), ly = fmaxf(a.y, gb.y);
                float rx = fminf(a.z, gb.z), ry = fminf(a.w, gb.w);
                float w = fmaxf(__fadd_rn(rx, -lx), 0.0f);
                float h = fmaxf(__fadd_rn(ry, -ly), 0.0f);
                float inter = __fmul_rn(w, h);
                float area_a = __fmul_rn(__fadd_rn(a.z, -a.x), __fadd_rn(a.w, -a.y));
                float uni = __fadd_rn(__fadd_rn(area_a, area_g), -inter);
                float iou = __fdiv_rn(inter, fmaxf(uni, 1e-12f));
                if (iou >= thr) atomicMax(&rF_best[rF_bi[slot]], g);
            }
        }
    }
}

__device__ const float4* rF_anchors_p;
__global__ void rF_setp(const float4* anchors) {
    if (threadIdx.x == 0 && blockIdx.x == 0) rF_anchors_p = anchors;
}

// K6: finalize — matched IoU recomputed exactly; [matched | max_ious] as f32
__global__ __launch_bounds__(256) void rF_final(
    const float4* __restrict__ anchors,
    const float4* __restrict__ gts,
    int N, int out_elems,
    float* __restrict__ out)
{
    int i = blockIdx.x * blockDim.x + threadIdx.x;
    if (i >= N) return;
    int g = rF_best[i];
    float iou_out = 0.0f;
    if (g >= 0) {
        float4 a = anchors[i];
        float4 gb = gts[g];
        float lx = fmaxf(a.x, gb.x), ly = fmaxf(a.y, gb.y);
        float rx = fminf(a.z, gb.z), ry = fminf(a.w, gb.w);
        float w = fmaxf(__fadd_rn(rx, -lx), 0.0f);
        float h = fmaxf(__fadd_rn(ry, -ly), 0.0f);
        float inter = __fmul_rn(w, h);
        float area_a = __fmul_rn(__fadd_rn(a.z, -a.x), __fadd_rn(a.w, -a.y));
        float area_g = __fmul_rn(__fadd_rn(gb.z, -gb.x), __fadd_rn(gb.w, -gb.y));
        float uni = __fadd_rn(__fadd_rn(area_a, area_g), -inter);
        iou_out = __fdiv_rn(inter, fmaxf(uni, 1e-12f));
    }
    if (i < out_elems)     out[i]     = (float)g;
    if (N + i < out_elems) out[N + i] = iou_out;
}

// ---------------------------------------------------------------------------
extern "C" void kernel_launch(void* const* d_in, const int* in_sizes, int n_in,
                              void* d_out, int out_size) {
    int ia = 0, ig = 1;
    if (n_in >= 2 && in_sizes[1] > in_sizes[0]) { ia = 1; ig = 0; }
    const float4* anchors = (const float4*)d_in[ia];
    const float4* gts     = (const float4*)d_in[ig];
    int N = in_sizes[ia] / 4; if (N > RF_MAXN) N = RF_MAXN;
    int M = in_sizes[ig] / 4; if (M > RF_MAXM) M = RF_MAXM;
    float* out = (float*)d_out;

    const int NB = (N + 255) / 256;
    rF_setp<<<1, 32>>>(anchors);
    rF_reset<<<(RF_NBIN + 255) / 256, 256>>>();
    rF_count<<<NB, 256>>>(anchors, N);
    rF_scan<<<1, 256>>>();
    rF_scatter<<<NB, 256>>>(anchors, N);
    rF_gt<<<(M + 7) / 8, 256>>>(gts, N, M);
    rF_final<<<NB, 256>>>(anchors, gts, N, out_size, out);
}

// round 16
// speedup vs baseline: 3.3178x; 1.0825x over previous
// rG — LDetection_12103217840297: fused warp-per-gt ATSS, 5-launch self-cleaning pipeline
#include <cuda_runtime.h>
#include <cstdint>
#include <math.h>

#define RG_MAXN 131072
#define RG_MAXM 1024
#define RG_K    9
#define RG_G    64
#define RG_NBIN (RG_G * RG_G)
#define RG_CELL 16.0f

// ---------------------------------------------------------------------------
// Scratch (__device__ globals; zero-initialized at module load)
// ---------------------------------------------------------------------------
__device__ int    rG_cnt[RG_NBIN];      // per-cell counts (self-cleaned by scan)
__device__ int    rG_off[RG_NBIN + 1];  // CSR offsets
__device__ int    rG_cell[RG_MAXN];     // cell id per anchor
__device__ int    rG_rank[RG_MAXN];     // rank within cell per anchor
__device__ float2 rG_bc[RG_MAXN];       // binned centers
__device__ int    rG_bi[RG_MAXN];       // binned anchor indices
__device__ float4 rG_ba[RG_MAXN];       // binned anchor boxes
__device__ int    rG_best[RG_MAXN];     // matched gt per anchor (atomicMax)

__device__ __forceinline__ int rG_cellidx(float v) {
    int c = (int)floorf(__fmul_rn(v, 1.0f / RG_CELL));
    return min(RG_G - 1, max(0, c));
}

// ---------------------------------------------------------------------------
// K1: best=-1, cell id + within-cell rank via the single atomic pass
// ---------------------------------------------------------------------------
__global__ void rG_count(const float4* __restrict__ anchors, int N) {
    int i = blockIdx.x * blockDim.x + threadIdx.x;
    if (i >= N) return;
    rG_best[i] = -1;
    float4 a = anchors[i];
    float cx = __fmul_rn(__fadd_rn(a.x, a.z), 0.5f);
    float cy = __fmul_rn(__fadd_rn(a.y, a.w), 0.5f);
    int cell = rG_cellidx(cy) * RG_G + rG_cellidx(cx);
    rG_cell[i] = cell;
    rG_rank[i] = atomicAdd(&rG_cnt[cell], 1);
}

// ---------------------------------------------------------------------------
// K2: warp-shuffle exclusive scan of 4096 counts (256 thr x 16 bins),
// then zero rG_cnt for the NEXT graph replay (self-cleaning).
// ---------------------------------------------------------------------------
__global__ __launch_bounds__(256) void rG_scan() {
    __shared__ int s_warp[8];
    const int t = threadIdx.x;
    const int lane = t & 31, wid = t >> 5;

    int loc[16];
    int tot = 0;
#pragma unroll
    for (int j = 0; j < 16; j++) {
        int c = rG_cnt[t * 16 + j];
        rG_cnt[t * 16 + j] = 0;          // self-clean for next replay
        loc[j] = tot;
        tot += c;
    }
    // inclusive warp scan of per-thread totals
    int scan = tot;
#pragma unroll
    for (int o = 1; o < 32; o <<= 1) {
        int v = __shfl_up_sync(0xFFFFFFFFu, scan, o);
        if (lane >= o) scan += v;
    }
    if (lane == 31) s_warp[wid] = scan;
    __syncthreads();
    if (wid == 0) {
        int w = (lane < 8) ? s_warp[lane] : 0;
#pragma unroll
        for (int o = 1; o < 8; o <<= 1) {
            int v = __shfl_up_sync(0xFFFFFFFFu, w, o);
            if (lane >= o) w += v;
        }
        if (lane < 8) s_warp[lane] = w;
    }
    __syncthreads();
    int base = (scan - tot) + ((wid > 0) ? s_warp[wid - 1] : 0);  // exclusive
#pragma unroll
    for (int j = 0; j < 16; j++)
        rG_off[t * 16 + j] = base + loc[j];
    if (t == 255) rG_off[RG_NBIN] = base + tot;
}

// ---------------------------------------------------------------------------
// K3: pure scatter — slot = off[cell] + rank (no atomics). Slot order within a
// cell is replay-non-deterministic, but all consumers are order-independent.
// ---------------------------------------------------------------------------
__global__ void rG_scatter(const float4* __restrict__ anchors, int N) {
    int i = blockIdx.x * blockDim.x + threadIdx.x;
    if (i >= N) return;
    float4 a = anchors[i];
    float cx = __fmul_rn(__fadd_rn(a.x, a.z), 0.5f);
    float cy = __fmul_rn(__fadd_rn(a.y, a.w), 0.5f);
    int slot = rG_off[rG_cell[i]] + rG_rank[i];
    rG_bc[slot] = make_float2(cx, cy);
    rG_bi[slot] = i;
    rG_ba[slot] = a;
}

// ---------------------------------------------------------------------------
// K4: fused per-gt kernel, ONE WARP PER GT.
//  A: expanding-ring exact top-9 by (f32 sqrt-distance, low idx) == lax.top_k
//     with stable ties. Lanes stride slots (coalesced); register-resident
//     sorted list of packed u64 keys; ring-end merge = 9 warp-min rounds on a
//     copy. Unscanned cells after ring r are >= r*CELL away: break when
//     r*CELL > d9 (strict).
//  B: thr = mean + std(ddof=1) of the 9 IoUs, sequential f32 (jnp order).
//  C: assignment over cells overlapping the gt box:
//     center-inside && iou >= thr  =>  atomicMax(best[anchor], g).
// ---------------------------------------------------------------------------
__global__ __launch_bounds__(256) void rG_gt(
    const float4* __restrict__ anchors,
    const float4* __restrict__ gts, int N, int M)
{
    const int warp = blockIdx.x * (blockDim.x >> 5) + (threadIdx.x >> 5);
    const int lane = threadIdx.x & 31;
    if (warp >= M) return;
    const int g = warp;

    const float4 gb = gts[g];
    const float gcx = __fmul_rn(__fadd_rn(gb.x, gb.z), 0.5f);
    const float gcy = __fmul_rn(__fadd_rn(gb.y, gb.w), 0.5f);
    const int ccx = rG_cellidx(gcx);
    const int ccy = rG_cellidx(gcy);

    const unsigned long long SENT = 0xFFFFFFFFFFFFFFFFull;
    unsigned long long K[RG_K];
#pragma unroll
    for (int j = 0; j < RG_K; j++) K[j] = SENT;

    auto scan_cell = [&](int cx, int cy) {
        int cell = cy * RG_G + cx;
        int s = rG_off[cell], e = rG_off[cell + 1];
        for (int slot = s + lane; slot < e; slot += 32) {
            float2 c = rG_bc[slot];
            int idx = rG_bi[slot];
            float dx = __fadd_rn(c.x, -gcx);
            float dy = __fadd_rn(c.y, -gcy);
            float d2 = __fadd_rn(__fmul_rn(dx, dx), __fmul_rn(dy, dy));
            float d = __fsqrt_rn(d2);
            unsigned long long key =
                ((unsigned long long)__float_as_uint(d) << 32) | (unsigned)idx;
            if (key < K[RG_K - 1]) {
                K[RG_K - 1] = key;
#pragma unroll
                for (int j = RG_K - 1; j > 0; j--) {
                    unsigned long long lo = K[j - 1], hi = K[j];
                    if (hi < lo) { K[j - 1] = hi; K[j] = lo; }
                }
            }
        }
    };

    unsigned long long sel[RG_K];
    auto merge = [&]() {
        unsigned long long T[RG_K];
#pragma unroll
        for (int j = 0; j < RG_K; j++) T[j] = K[j];
#pragma unroll
        for (int t = 0; t < RG_K; t++) {
            unsigned long long m = T[0];
#pragma unroll
            for (int o = 16; o > 0; o >>= 1) {
                unsigned long long v = __shfl_xor_sync(0xFFFFFFFFu, m, o);
                if (v < m) m = v;
            }
            if (T[0] == m) {             // keys unique (idx in low bits)
#pragma unroll
                for (int j = 0; j < RG_K - 1; j++) T[j] = T[j + 1];
                T[RG_K - 1] = SENT;
            }
            sel[t] = m;                  // butterfly leaves min in all lanes
        }
    };

    for (int r = 0; r <= 2 * RG_G; r++) {
        if (r == 0) {
            scan_cell(ccx, ccy);
        } else {
            int x0 = ccx - r, x1 = ccx + r, y0 = ccy - r, y1 = ccy + r;
            int xa = max(x0, 0), xb = min(x1, RG_G - 1);
            if (y0 >= 0)        for (int x = xa; x <= xb; x++) scan_cell(x, y0);
            if (y1 <= RG_G - 1) for (int x = xa; x <= xb; x++) scan_cell(x, y1);
            int ya = max(y0 + 1, 0), yb = min(y1 - 1, RG_G - 1);
            if (x0 >= 0)        for (int y = ya; y <= yb; y++) scan_cell(x0, y);
            if (x1 <= RG_G - 1) for (int y = ya; y <= yb; y++) scan_cell(x1, y);
        }
        if (r >= 2) {
            merge();
            if (sel[RG_K - 1] != SENT) {
                float d9 = __uint_as_float((unsigned)(sel[RG_K - 1] >> 32));
                if (__fmul_rn((float)r, RG_CELL) > d9) break;
            }
        }
    }

    // Phase B: IoU per selected anchor in lanes 0..8; thr identical in all lanes
    const float area_g = __fmul_rn(__fadd_rn(gb.z, -gb.x), __fadd_rn(gb.w, -gb.y));
    float my_iou = 0.0f;
    if (lane < RG_K) {
        int idx = (int)(unsigned)(sel[lane] & 0xFFFFFFFFull);
        if (idx < 0 || idx >= N) idx = 0;   // unreachable guard
        float4 a = anchors[idx];
        float lx = fmaxf(a.x, gb.x), ly = fmaxf(a.y, gb.y);
        float rx = fminf(a.z, gb.z), ry = fminf(a.w, gb.w);
        float w = fmaxf(__fadd_rn(rx, -lx), 0.0f);
        float h = fmaxf(__fadd_rn(ry, -ly), 0.0f);
        float inter = __fmul_rn(w, h);
        float area_a = __fmul_rn(__fadd_rn(a.z, -a.x), __fadd_rn(a.w, -a.y));
        float uni = __fadd_rn(__fadd_rn(area_a, area_g), -inter);
        my_iou = __fdiv_rn(inter, fmaxf(uni, 1e-12f));
    }
    float thr;
    {
        float iou_t[RG_K];
#pragma unroll
        for (int t = 0; t < RG_K; t++)
            iou_t[t] = __shfl_sync(0xFFFFFFFFu, my_iou, t);
        float sum = 0.0f;
#pragma unroll
        for (int t = 0; t < RG_K; t++) sum = __fadd_rn(sum, iou_t[t]);
        float mean = __fdiv_rn(sum, (float)RG_K);
        float ss = 0.0f;
#pragma unroll
        for (int t = 0; t < RG_K; t++) {
            float d = __fadd_rn(iou_t[t], -mean);
            ss = __fadd_rn(ss, __fmul_rn(d, d));
        }
        float var = __fdiv_rn(ss, (float)(RG_K - 1));
        thr = __fadd_rn(mean, __fsqrt_rn(var));
    }

    // Phase C: assignment over cells overlapping the gt box
    const int cx0 = rG_cellidx(gb.x), cx1 = rG_cellidx(gb.z);
    const int cy0 = rG_cellidx(gb.y), cy1 = rG_cellidx(gb.w);
    for (int cy = cy0; cy <= cy1; cy++) {
        for (int cx = cx0; cx <= cx1; cx++) {
            int cell = cy * RG_G + cx;
            int s = rG_off[cell], e = rG_off[cell + 1];
            for (int slot = s + lane; slot < e; slot += 32) {
                float2 c = rG_bc[slot];
                bool inside = (c.x >= gb.x) && (c.x <= gb.z) &&
                              (c.y >= gb.y) && (c.y <= gb.w);
                if (!inside) continue;
                float4 a = rG_ba[slot];
                float lx = fmaxf(a.x, gb.x), ly = fmaxf(a.y, gb.y);
                float rx = fminf(a.z, gb.z), ry = fminf(a.w, gb.w);
                float w = fmaxf(__fadd_rn(rx, -lx), 0.0f);
                float h = fmaxf(__fadd_rn(ry, -ly), 0.0f);
                float inter = __fmul_rn(w, h);
                float area_a = __fmul_rn(__fadd_rn(a.z, -a.x), __fadd_rn(a.w, -a.y));
                float uni = __fadd_rn(__fadd_rn(area_a, area_g), -inter);
                float iou = __fdiv_rn(inter, fmaxf(uni, 1e-12f));
                if (iou >= thr) atomicMax(&rG_best[rG_bi[slot]], g);
            }
        }
    }
}

// ---------------------------------------------------------------------------
// K5: finalize — matched IoU recomputed exactly; [matched | max_ious] as f32
// ---------------------------------------------------------------------------
__global__ __launch_bounds__(256) void rG_final(
    const float4* __restrict__ anchors,
    const float4* __restrict__ gts,
    int N, int out_elems,
    float* __restrict__ out)
{
    int i = blockIdx.x * blockDim.x + threadIdx.x;
    if (i >= N) return;
    int g = rG_best[i];
    float iou_out = 0.0f;
    if (g >= 0) {
        float4 a = anchors[i];
        float4 gb = gts[g];
        float lx = fmaxf(a.x, gb.x), ly = fmaxf(a.y, gb.y);
        float rx = fminf(a.z, gb.z), ry = fminf(a.w, gb.w);
        float w = fmaxf(__fadd_rn(rx, -lx), 0.0f);
        float h = fmaxf(__fadd_rn(ry, -ly), 0.0f);
        float inter = __fmul_rn(w, h);
        float area_a = __fmul_rn(__fadd_rn(a.z, -a.x), __fadd_rn(a.w, -a.y));
        float area_g = __fmul_rn(__fadd_rn(gb.z, -gb.x), __fadd_rn(gb.w, -gb.y));
        float uni = __fadd_rn(__fadd_rn(area_a, area_g), -inter);
        iou_out = __fdiv_rn(inter, fmaxf(uni, 1e-12f));
    }
    if (i < out_elems)     out[i]     = (float)g;
    if (N + i < out_elems) out[N + i] = iou_out;
}

// ---------------------------------------------------------------------------
extern "C" void kernel_launch(void* const* d_in, const int* in_sizes, int n_in,
                              void* d_out, int out_size) {
    int ia = 0, ig = 1;
    if (n_in >= 2 && in_sizes[1] > in_sizes[0]) { ia = 1; ig = 0; }
    const float4* anchors = (const float4*)d_in[ia];
    const float4* gts     = (const float4*)d_in[ig];
    int N = in_sizes[ia] / 4; if (N > RG_MAXN) N = RG_MAXN;
    int M = in_sizes[ig] / 4; if (M > RG_MAXM) M = RG_MAXM;
    float* out = (float*)d_out;

    const int NB = (N + 255) / 256;
    rG_count<<<NB, 256>>>(anchors, N);
    rG_scan<<<1, 256>>>();
    rG_scatter<<<NB, 256>>>(anchors, N);
    rG_gt<<<(M + 7) / 8, 256>>>(anchors, gts, N, M);
    rG_final<<<NB, 256>>>(anchors, gts, N, out_size, out);
}

// round 17
// speedup vs baseline: 4.0630x; 1.2246x over previous
// rH — LDetection_12103217840297: warp-per-gt ATSS, row-range CSR scans,
// r=1 early exit, 1-warp blocks for full-SM spread. f32 output, exact.
#include <cuda_runtime.h>
#include <cstdint>
#include <math.h>

#define RH_MAXN 131072
#define RH_MAXM 1024
#define RH_K    9
#define RH_G    64
#define RH_NBIN (RH_G * RH_G)
#define RH_CELL 16.0f

// ---------------------------------------------------------------------------
// Scratch (__device__ globals; zero-initialized at module load)
// ---------------------------------------------------------------------------
__device__ int    rH_cnt[RH_NBIN];      // per-cell counts (self-cleaned by scan)
__device__ int    rH_off[RH_NBIN + 1];  // CSR offsets
__device__ int    rH_cell[RH_MAXN];     // cell id per anchor
__device__ int    rH_rank[RH_MAXN];     // rank within cell
__device__ float2 rH_bc[RH_MAXN];       // binned centers
__device__ int    rH_bi[RH_MAXN];       // binned anchor indices
__device__ float4 rH_ba[RH_MAXN];       // binned anchor boxes
__device__ int    rH_best[RH_MAXN];     // matched gt per anchor (atomicMax)

__device__ __forceinline__ int rH_cellidx(float v) {
    int c = (int)floorf(__fmul_rn(v, 1.0f / RH_CELL));
    return min(RH_G - 1, max(0, c));
}

// K1: best=-1; cell id + within-cell rank (single atomic pass)
__global__ void rH_count(const float4* __restrict__ anchors, int N) {
    int i = blockIdx.x * blockDim.x + threadIdx.x;
    if (i >= N) return;
    rH_best[i] = -1;
    float4 a = anchors[i];
    float cx = __fmul_rn(__fadd_rn(a.x, a.z), 0.5f);
    float cy = __fmul_rn(__fadd_rn(a.y, a.w), 0.5f);
    int cell = rH_cellidx(cy) * RH_G + rH_cellidx(cx);
    rH_cell[i] = cell;
    rH_rank[i] = atomicAdd(&rH_cnt[cell], 1);
}

// K2: warp-shuffle exclusive scan of 4096 counts; self-cleans rH_cnt
__global__ __launch_bounds__(256) void rH_scan() {
    __shared__ int s_warp[8];
    const int t = threadIdx.x;
    const int lane = t & 31, wid = t >> 5;
    int loc[16];
    int tot = 0;
#pragma unroll
    for (int j = 0; j < 16; j++) {
        int c = rH_cnt[t * 16 + j];
        rH_cnt[t * 16 + j] = 0;
        loc[j] = tot;
        tot += c;
    }
    int scan = tot;
#pragma unroll
    for (int o = 1; o < 32; o <<= 1) {
        int v = __shfl_up_sync(0xFFFFFFFFu, scan, o);
        if (lane >= o) scan += v;
    }
    if (lane == 31) s_warp[wid] = scan;
    __syncthreads();
    if (wid == 0) {
        int w = (lane < 8) ? s_warp[lane] : 0;
#pragma unroll
        for (int o = 1; o < 8; o <<= 1) {
            int v = __shfl_up_sync(0xFFFFFFFFu, w, o);
            if (lane >= o) w += v;
        }
        if (lane < 8) s_warp[lane] = w;
    }
    __syncthreads();
    int base = (scan - tot) + ((wid > 0) ? s_warp[wid - 1] : 0);
#pragma unroll
    for (int j = 0; j < 16; j++)
        rH_off[t * 16 + j] = base + loc[j];
    if (t == 255) rH_off[RH_NBIN] = base + tot;
}

// K3: pure scatter — slot = off[cell] + rank (no atomics). Slot order within a
// cell is non-deterministic; all consumers are order-independent.
__global__ void rH_scatter(const float4* __restrict__ anchors, int N) {
    int i = blockIdx.x * blockDim.x + threadIdx.x;
    if (i >= N) return;
    float4 a = anchors[i];
    float cx = __fmul_rn(__fadd_rn(a.x, a.z), 0.5f);
    float cy = __fmul_rn(__fadd_rn(a.y, a.w), 0.5f);
    int slot = rH_off[rH_cell[i]] + rH_rank[i];
    rH_bc[slot] = make_float2(cx, cy);
    rH_bi[slot] = i;
    rH_ba[slot] = a;
}

// ---------------------------------------------------------------------------
// K4: fused per-gt kernel, ONE WARP PER BLOCK (full-SM spread).
//  A: exact top-9 by (f32 sqrt-distance, low idx) == lax.top_k stable ties.
//     3x3 box scanned as 3 contiguous ROW-RANGES, early exit if CELL > d9;
//     rare expansion by true rings (no rescans => no duplicate keys).
//  B: thr = mean + std(ddof=1) of the 9 IoUs, sequential f32 (jnp order).
//  C: assignment — gt rectangle scanned as per-row ranges;
//     center-inside && iou >= thr => atomicMax(best[anchor], g).
// ---------------------------------------------------------------------------
__global__ __launch_bounds__(32) void rH_gt(
    const float4* __restrict__ anchors,
    const float4* __restrict__ gts, int N, int M)
{
    const int g = blockIdx.x;
    const int lane = threadIdx.x;
    if (g >= M) return;

    const float4 gb = gts[g];
    const float gcx = __fmul_rn(__fadd_rn(gb.x, gb.z), 0.5f);
    const float gcy = __fmul_rn(__fadd_rn(gb.y, gb.w), 0.5f);
    const int ccx = rH_cellidx(gcx);
    const int ccy = rH_cellidx(gcy);

    const unsigned long long SENT = 0xFFFFFFFFFFFFFFFFull;
    unsigned long long K[RH_K];
#pragma unroll
    for (int j = 0; j < RH_K; j++) K[j] = SENT;

    // scan one contiguous CSR range covering cells [c0 .. c1] (same row)
    auto scan_range = [&](int c0, int c1) {
        int s = rH_off[c0], e = rH_off[c1 + 1];
        for (int slot = s + lane; slot < e; slot += 32) {
            float2 c = rH_bc[slot];
            int idx = rH_bi[slot];
            float dx = __fadd_rn(c.x, -gcx);
            float dy = __fadd_rn(c.y, -gcy);
            float d2 = __fadd_rn(__fmul_rn(dx, dx), __fmul_rn(dy, dy));
            float d = __fsqrt_rn(d2);
            unsigned long long key =
                ((unsigned long long)__float_as_uint(d) << 32) | (unsigned)idx;
            if (key < K[RH_K - 1]) {
                K[RH_K - 1] = key;
#pragma unroll
                for (int j = RH_K - 1; j > 0; j--) {
                    unsigned long long lo = K[j - 1], hi = K[j];
                    if (hi < lo) { K[j - 1] = hi; K[j] = lo; }
                }
            }
        }
    };

    unsigned long long sel[RH_K];
    auto merge = [&]() {
        unsigned long long T[RH_K];
#pragma unroll
        for (int j = 0; j < RH_K; j++) T[j] = K[j];
#pragma unroll
        for (int t = 0; t < RH_K; t++) {
            unsigned long long m = T[0];
#pragma unroll
            for (int o = 16; o > 0; o >>= 1) {
                unsigned long long v = __shfl_xor_sync(0xFFFFFFFFu, m, o);
                if (v < m) m = v;
            }
            if (T[0] == m) {                 // keys unique (idx in low bits)
#pragma unroll
                for (int j = 0; j < RH_K - 1; j++) T[j] = T[j + 1];
                T[RH_K - 1] = SENT;
            }
            sel[t] = m;
        }
    };

    // Phase A: 3x3 box as 3 row-ranges, then rare ring expansion.
    {
        int xa = max(ccx - 1, 0), xb = min(ccx + 1, RH_G - 1);
        int ya = max(ccy - 1, 0), yb = min(ccy + 1, RH_G - 1);
        for (int y = ya; y <= yb; y++)
            scan_range(y * RH_G + xa, y * RH_G + xb);
        merge();
        bool done = (sel[RH_K - 1] != SENT) &&
                    (RH_CELL > __uint_as_float((unsigned)(sel[RH_K - 1] >> 32)));
        for (int r = 2; !done && r <= 2 * RH_G; r++) {
            int x0 = ccx - r, x1 = ccx + r, y0 = ccy - r, y1 = ccy + r;
            int rxa = max(x0, 0), rxb = min(x1, RH_G - 1);
            if (y0 >= 0)         scan_range(y0 * RH_G + rxa, y0 * RH_G + rxb);
            if (y1 <= RH_G - 1)  scan_range(y1 * RH_G + rxa, y1 * RH_G + rxb);
            int mya = max(y0 + 1, 0), myb = min(y1 - 1, RH_G - 1);
            for (int y = mya; y <= myb; y++) {
                if (x0 >= 0)        scan_range(y * RH_G + x0, y * RH_G + x0);
                if (x1 <= RH_G - 1) scan_range(y * RH_G + x1, y * RH_G + x1);
            }
            merge();
            done = (sel[RH_K - 1] != SENT) &&
                   (__fmul_rn((float)r, RH_CELL) >
                    __uint_as_float((unsigned)(sel[RH_K - 1] >> 32)));
        }
    }

    // Phase B: IoU of the 9 selected (lanes 0..8); thr via shuffle broadcast
    const float area_g = __fmul_rn(__fadd_rn(gb.z, -gb.x), __fadd_rn(gb.w, -gb.y));
    float my_iou = 0.0f;
    if (lane < RH_K) {
        int idx = (int)(unsigned)(sel[lane] & 0xFFFFFFFFull);
        if (idx < 0 || idx >= N) idx = 0;        // unreachable guard
        float4 a = anchors[idx];
        float lx = fmaxf(a.x, gb.x), ly = fmaxf(a.y, gb.y);
        float rx = fminf(a.z, gb.z), ry = fminf(a.w, gb.w);
        float w = fmaxf(__fadd_rn(rx, -lx), 0.0f);
        float h = fmaxf(__fadd_rn(ry, -ly), 0.0f);
        float inter = __fmul_rn(w, h);
        float area_a = __fmul_rn(__fadd_rn(a.z, -a.x), __fadd_rn(a.w, -a.y));
        float uni = __fadd_rn(__fadd_rn(area_a, area_g), -inter);
        my_iou = __fdiv_rn(inter, fmaxf(uni, 1e-12f));
    }
    float thr;
    {
        float iou_t[RH_K];
#pragma unroll
        for (int t = 0; t < RH_K; t++)
            iou_t[t] = __shfl_sync(0xFFFFFFFFu, my_iou, t);
        float sum = 0.0f;
#pragma unroll
        for (int t = 0; t < RH_K; t++) sum = __fadd_rn(sum, iou_t[t]);
        float mean = __fdiv_rn(sum, (float)RH_K);
        float ss = 0.0f;
#pragma unroll
        for (int t = 0; t < RH_K; t++) {
            float d = __fadd_rn(iou_t[t], -mean);
            ss = __fadd_rn(ss, __fmul_rn(d, d));
        }
        float var = __fdiv_rn(ss, (float)(RH_K - 1));
        thr = __fadd_rn(mean, __fsqrt_rn(var));
    }

    // Phase C: assignment — per-row contiguous ranges over the gt rectangle
    const int cx0 = rH_cellidx(gb.x), cx1 = rH_cellidx(gb.z);
    const int cy0 = rH_cellidx(gb.y), cy1 = rH_cellidx(gb.w);
    for (int cy = cy0; cy <= cy1; cy++) {
        int s = rH_off[cy * RH_G + cx0], e = rH_off[cy * RH_G + cx1 + 1];
        for (int slot = s + lane; slot < e; slot += 32) {
            float2 c = rH_bc[slot];
            bool inside = (c.x >= gb.x) && (c.x <= gb.z) &&
                          (c.y >= gb.y) && (c.y <= gb.w);
            if (!inside) continue;
            float4 a = rH_ba[slot];
            float lx = fmaxf(a.x, gb.x), ly = fmaxf(a.y, gb.y);
            float rx = fminf(a.z, gb.z), ry = fminf(a.w, gb.w);
            float w = fmaxf(__fadd_rn(rx, -lx), 0.0f);
            float h = fmaxf(__fadd_rn(ry, -ly), 0.0f);
            float inter = __fmul_rn(w, h);
            float area_a = __fmul_rn(__fadd_rn(a.z, -a.x), __fadd_rn(a.w, -a.y));
            float uni = __fadd_rn(__fadd_rn(area_a, area_g), -inter);
            float iou = __fdiv_rn(inter, fmaxf(uni, 1e-12f));
            if (iou >= thr) atomicMax(&rH_best[rH_bi[slot]], g);
        }
    }
}

// K5: finalize — matched IoU recomputed exactly; [matched | max_ious] as f32
__global__ __launch_bounds__(256) void rH_final(
    const float4* __restrict__ anchors,
    const float4* __restrict__ gts,
    int N, int out_elems,
    float* __restrict__ out)
{
    int i = blockIdx.x * blockDim.x + threadIdx.x;
    if (i >= N) return;
    int g = rH_best[i];
    float iou_out = 0.0f;
    if (g >= 0) {
        float4 a = anchors[i];
        float4 gb = gts[g];
        float lx = fmaxf(a.x, gb.x), ly = fmaxf(a.y, gb.y);
        float rx = fminf(a.z, gb.z), ry = fminf(a.w, gb.w);
        float w = fmaxf(__fadd_rn(rx, -lx), 0.0f);
        float h = fmaxf(__fadd_rn(ry, -ly), 0.0f);
        float inter = __fmul_rn(w, h);
        float area_a = __fmul_rn(__fadd_rn(a.z, -a.x), __fadd_rn(a.w, -a.y));
        float area_g = __fmul_rn(__fadd_rn(gb.z, -gb.x), __fadd_rn(gb.w, -gb.y));
        float uni = __fadd_rn(__fadd_rn(area_a, area_g), -inter);
        iou_out = __fdiv_rn(inter, fmaxf(uni, 1e-12f));
    }
    if (i < out_elems)     out[i]     = (float)g;
    if (N + i < out_elems) out[N + i] = iou_out;
}

// ---------------------------------------------------------------------------
extern "C" void kernel_launch(void* const* d_in, const int* in_sizes, int n_in,
                              void* d_out, int out_size) {
    int ia = 0, ig = 1;
    if (n_in >= 2 && in_sizes[1] > in_sizes[0]) { ia = 1; ig = 0; }
    const float4* anchors = (const float4*)d_in[ia];
    const float4* gts     = (const float4*)d_in[ig];
    int N = in_sizes[ia] / 4; if (N > RH_MAXN) N = RH_MAXN;
    int M = in_sizes[ig] / 4; if (M > RH_MAXM) M = RH_MAXM;
    float* out = (float*)d_out;

    const int NB = (N + 255) / 256;
    rH_count<<<NB, 256>>>(anchors, N);
    rH_scan<<<1, 256>>>();
    rH_scatter<<<NB, 256>>>(anchors, N);
    rH_gt<<<M, 32>>>(anchors, gts, N, M);
    rH_final<<<NB, 256>>>(anchors, gts, N, out_size, out);
}